// round 2
// baseline (speedup 1.0000x reference)
#include <cuda_runtime.h>
#include <math.h>

// Problem constants (fixed by setup_inputs)
#define BB   4096
#define CX   64
#define UU   128
#define NN   36
#define CC   192          // CX + UU
#define ORD  4            // order+1 diffusion levels (incl. self)
#define CCAT 768          // ORD * CC
#define NPAD 40           // padded Z row length (smem)
#define ASP  37           // padded adj row length (conflict-free hop)
#define XSP  37           // padded x-copy row length

// Transposed weights [cc][o] (device globals: allocation-free)
__device__ float g_Wt_f[CCAT * UU];
__device__ float g_Wt_u[CCAT * UU];
__device__ float g_Wt_c[CCAT * UU];

// ---------------------------------------------------------------------------
// Transpose the three weight matrices [128, 768] -> [768, 128]
// ---------------------------------------------------------------------------
__global__ void transpose_w_kernel(const float* __restrict__ Wf,
                                   const float* __restrict__ Wu,
                                   const float* __restrict__ Wc) {
    int i = blockIdx.x * blockDim.x + threadIdx.x;   // over CCAT*UU
    if (i >= CCAT * UU) return;
    int cc = i / UU;
    int o  = i - cc * UU;
    int src = o * CCAT + cc;                          // W is [o][cc]
    g_Wt_f[i] = Wf[src];
    g_Wt_u[i] = Wu[src];
    g_Wt_c[i] = Wc[src];
}

// ---------------------------------------------------------------------------
// Fused GCGRU cell. One CTA per batch element.
//   Phase 1: Z=[x;h], 4 diffusion levels (in-place hops), accumulate the
//            f and u gate GEMVs level-by-level -> r,u.
//   Phase 2: Z=[x;r*h], same diffusion, W_c GEMV -> candidate c.
//   Output:  u*h + (1-u)*tanh(c).
// Thread map: 256 threads; o = tid & 127 (output channel), n-half = tid>>7.
// ---------------------------------------------------------------------------
__global__ void __launch_bounds__(256) gcgru_fused_kernel(
        const float* __restrict__ x, const float* __restrict__ h,
        const float* __restrict__ adj,
        const float* __restrict__ b_f, const float* __restrict__ b_u,
        const float* __restrict__ b_c, float* __restrict__ out) {
    __shared__ float Z [CC * NPAD];    // working tile [192][40]
    __shared__ float As[NN * ASP];     // adjacency    [36][37]
    __shared__ float Xs[CX * XSP];     // x copy       [64][37]

    const int b   = blockIdx.x;
    const int tid = threadIdx.x;
    const int o   = tid & 127;
    const int nb  = (tid >> 7) * 18;   // 0 or 18

    // ---------------- load inputs ----------------
    const float* xb = x + (size_t)b * CX * NN;
    for (int i = tid; i < CX * NN; i += 256) {
        int c = i / NN, n = i - c * NN;
        float v = xb[i];
        Z[c * NPAD + n]  = v;
        Xs[c * XSP + n]  = v;
    }
    const float* hb = h + (size_t)b * UU * NN;
    for (int i = tid; i < UU * NN; i += 256) {
        int c = i / NN, n = i - c * NN;
        Z[(CX + c) * NPAD + n] = hb[i];
    }
    for (int i = tid; i < NN * NN; i += 256) {
        int w = i / NN, n = i - w * NN;
        As[w * ASP + n] = adj[i];
    }

    // this thread's slice of h (survives both phases in registers)
    float hreg[18];
    {
        const float* hp = hb + o * NN + nb;
#pragma unroll
        for (int j = 0; j < 18; j++) hreg[j] = hp[j];
    }

    // ================= phase 1: gates =================
    float accf[18], accu[18];
#pragma unroll
    for (int j = 0; j < 18; j++) { accf[j] = 0.f; accu[j] = 0.f; }

    for (int k = 0; k < ORD; k++) {
        __syncthreads();   // Z level-k ready

        const float* wf = g_Wt_f + k * CC * UU + o;
        const float* wu = g_Wt_u + k * CC * UU + o;
#pragma unroll 4
        for (int c = 0; c < CC; c++) {
            float wfv = wf[c * UU];
            float wuv = wu[c * UU];
            const float2* zr = (const float2*)(Z + c * NPAD + nb);
#pragma unroll
            for (int j2 = 0; j2 < 9; j2++) {
                float2 z = zr[j2];
                accf[2 * j2]     += wfv * z.x;
                accf[2 * j2 + 1] += wfv * z.y;
                accu[2 * j2]     += wuv * z.x;
                accu[2 * j2 + 1] += wuv * z.y;
            }
        }

        if (k < ORD - 1) {
            // in-place hop: Z[c][w] <- sum_n Z[c][n] * adj[w][n]
            float tmp[27];                         // 192*36/256 = 27
#pragma unroll
            for (int i = 0; i < 27; i++) {
                int e = tid + i * 256;
                int c = e / NN, w = e - c * NN;
                const float* zr = Z + c * NPAD;
                const float* ar = As + w * ASP;
                float s = 0.f;
#pragma unroll
                for (int n = 0; n < NN; n++) s += zr[n] * ar[n];
                tmp[i] = s;
            }
            __syncthreads();
#pragma unroll
            for (int i = 0; i < 27; i++) {
                int e = tid + i * 256;
                int c = e / NN, w = e - c * NN;
                Z[c * NPAD + w] = tmp[i];
            }
        }
    }

    // gates: r = sigmoid(accf + b_f), u = sigmoid(accu + b_u)
    const float bfv = b_f[o];
    const float buv = b_u[o];
    float ureg[18], rh[18];
#pragma unroll
    for (int j = 0; j < 18; j++) {
        float r = 1.f / (1.f + expf(-(accf[j] + bfv)));
        ureg[j] = 1.f / (1.f + expf(-(accu[j] + buv)));
        rh[j]   = r * hreg[j];
    }

    // ================= rebuild Z = [x ; r*h] =================
    __syncthreads();   // all phase-1 reads of Z done
    for (int i = tid; i < CX * NN; i += 256) {
        int c = i / NN, n = i - c * NN;
        Z[c * NPAD + n] = Xs[c * XSP + n];
    }
    {
        float* zp = Z + (CX + o) * NPAD + nb;
#pragma unroll
        for (int j = 0; j < 18; j++) zp[j] = rh[j];
    }

    // ================= phase 2: candidate =================
    float accc[18];
#pragma unroll
    for (int j = 0; j < 18; j++) accc[j] = 0.f;

    for (int k = 0; k < ORD; k++) {
        __syncthreads();

        const float* wc = g_Wt_c + k * CC * UU + o;
#pragma unroll 4
        for (int c = 0; c < CC; c++) {
            float wcv = wc[c * UU];
            const float2* zr = (const float2*)(Z + c * NPAD + nb);
#pragma unroll
            for (int j2 = 0; j2 < 9; j2++) {
                float2 z = zr[j2];
                accc[2 * j2]     += wcv * z.x;
                accc[2 * j2 + 1] += wcv * z.y;
            }
        }

        if (k < ORD - 1) {
            float tmp[27];
#pragma unroll
            for (int i = 0; i < 27; i++) {
                int e = tid + i * 256;
                int c = e / NN, w = e - c * NN;
                const float* zr = Z + c * NPAD;
                const float* ar = As + w * ASP;
                float s = 0.f;
#pragma unroll
                for (int n = 0; n < NN; n++) s += zr[n] * ar[n];
                tmp[i] = s;
            }
            __syncthreads();
#pragma unroll
            for (int i = 0; i < 27; i++) {
                int e = tid + i * 256;
                int c = e / NN, w = e - c * NN;
                Z[c * NPAD + w] = tmp[i];
            }
        }
    }

    // ================= output =================
    const float bcv = b_c[o];
    float* op = out + ((size_t)b * UU + o) * NN + nb;
#pragma unroll
    for (int j = 0; j < 18; j++) {
        float c = tanhf(accc[j] + bcv);
        float u = ureg[j];
        op[j] = u * hreg[j] + (1.f - u) * c;
    }
}

// ---------------------------------------------------------------------------
// Launch (graph-capturable: kernel launches only)
// ---------------------------------------------------------------------------
extern "C" void kernel_launch(void* const* d_in, const int* in_sizes, int n_in,
                              void* d_out, int out_size) {
    const float* x   = (const float*)d_in[0];   // [4096, 64, 36]
    const float* h   = (const float*)d_in[1];   // [4096, 128, 36]
    const float* adj = (const float*)d_in[2];   // [36, 36]
    const float* W_f = (const float*)d_in[3];   // [128, 768]
    const float* b_f = (const float*)d_in[4];   // [128]
    const float* W_u = (const float*)d_in[5];
    const float* b_u = (const float*)d_in[6];
    const float* W_c = (const float*)d_in[7];
    const float* b_c = (const float*)d_in[8];
    float* out = (float*)d_out;                 // [4096, 128, 36]

    transpose_w_kernel<<<(CCAT * UU + 255) / 256, 256>>>(W_f, W_u, W_c);
    gcgru_fused_kernel<<<BB, 256>>>(x, h, adj, b_f, b_u, b_c, out);
}

// round 3
// speedup vs baseline: 1.0001x; 1.0001x over previous
#include <cuda_runtime.h>
#include <math.h>

// Problem constants (fixed by setup_inputs)
#define BB   4096
#define CX   64
#define UU   128
#define NN   36
#define CC   192          // CX + UU
#define ORD  4            // order+1 diffusion levels (incl. self)
#define CCAT 768          // ORD * CC
#define NPAD 40           // padded Z row length (smem)
#define ASP  37           // padded adj row length (conflict-free hop)
#define XSP  37           // padded x-copy row length

// Transposed weights [cc][o] (device globals: allocation-free)
__device__ float g_Wt_f[CCAT * UU];
__device__ float g_Wt_u[CCAT * UU];
__device__ float g_Wt_c[CCAT * UU];

// ---------------------------------------------------------------------------
// Transpose the three weight matrices [128, 768] -> [768, 128]
// ---------------------------------------------------------------------------
__global__ void transpose_w_kernel(const float* __restrict__ Wf,
                                   const float* __restrict__ Wu,
                                   const float* __restrict__ Wc) {
    int i = blockIdx.x * blockDim.x + threadIdx.x;   // over CCAT*UU
    if (i >= CCAT * UU) return;
    int cc = i / UU;
    int o  = i - cc * UU;
    int src = o * CCAT + cc;                          // W is [o][cc]
    g_Wt_f[i] = Wf[src];
    g_Wt_u[i] = Wu[src];
    g_Wt_c[i] = Wc[src];
}

// ---------------------------------------------------------------------------
// Fused GCGRU cell. One CTA per batch element.
//   Phase 1: Z=[x;h], 4 diffusion levels (in-place hops), accumulate the
//            f and u gate GEMVs level-by-level -> r,u.
//   Phase 2: Z=[x;r*h], same diffusion, W_c GEMV -> candidate c.
//   Output:  u*h + (1-u)*tanh(c).
// Thread map: 256 threads; o = tid & 127 (output channel), n-half = tid>>7.
// ---------------------------------------------------------------------------
__global__ void __launch_bounds__(256) gcgru_fused_kernel(
        const float* __restrict__ x, const float* __restrict__ h,
        const float* __restrict__ adj,
        const float* __restrict__ b_f, const float* __restrict__ b_u,
        const float* __restrict__ b_c, float* __restrict__ out) {
    __shared__ float Z [CC * NPAD];    // working tile [192][40]
    __shared__ float As[NN * ASP];     // adjacency    [36][37]
    __shared__ float Xs[CX * XSP];     // x copy       [64][37]

    const int b   = blockIdx.x;
    const int tid = threadIdx.x;
    const int o   = tid & 127;
    const int nb  = (tid >> 7) * 18;   // 0 or 18

    // ---------------- load inputs ----------------
    const float* xb = x + (size_t)b * CX * NN;
    for (int i = tid; i < CX * NN; i += 256) {
        int c = i / NN, n = i - c * NN;
        float v = xb[i];
        Z[c * NPAD + n]  = v;
        Xs[c * XSP + n]  = v;
    }
    const float* hb = h + (size_t)b * UU * NN;
    for (int i = tid; i < UU * NN; i += 256) {
        int c = i / NN, n = i - c * NN;
        Z[(CX + c) * NPAD + n] = hb[i];
    }
    for (int i = tid; i < NN * NN; i += 256) {
        int w = i / NN, n = i - w * NN;
        As[w * ASP + n] = adj[i];
    }

    // this thread's slice of h (survives both phases in registers)
    float hreg[18];
    {
        const float* hp = hb + o * NN + nb;
#pragma unroll
        for (int j = 0; j < 18; j++) hreg[j] = hp[j];
    }

    // ================= phase 1: gates =================
    float accf[18], accu[18];
#pragma unroll
    for (int j = 0; j < 18; j++) { accf[j] = 0.f; accu[j] = 0.f; }

    for (int k = 0; k < ORD; k++) {
        __syncthreads();   // Z level-k ready

        const float* wf = g_Wt_f + k * CC * UU + o;
        const float* wu = g_Wt_u + k * CC * UU + o;
#pragma unroll 4
        for (int c = 0; c < CC; c++) {
            float wfv = wf[c * UU];
            float wuv = wu[c * UU];
            const float2* zr = (const float2*)(Z + c * NPAD + nb);
#pragma unroll
            for (int j2 = 0; j2 < 9; j2++) {
                float2 z = zr[j2];
                accf[2 * j2]     += wfv * z.x;
                accf[2 * j2 + 1] += wfv * z.y;
                accu[2 * j2]     += wuv * z.x;
                accu[2 * j2 + 1] += wuv * z.y;
            }
        }

        if (k < ORD - 1) {
            // in-place hop: Z[c][w] <- sum_n Z[c][n] * adj[w][n]
            float tmp[27];                         // 192*36/256 = 27
#pragma unroll
            for (int i = 0; i < 27; i++) {
                int e = tid + i * 256;
                int c = e / NN, w = e - c * NN;
                const float* zr = Z + c * NPAD;
                const float* ar = As + w * ASP;
                float s = 0.f;
#pragma unroll
                for (int n = 0; n < NN; n++) s += zr[n] * ar[n];
                tmp[i] = s;
            }
            __syncthreads();
#pragma unroll
            for (int i = 0; i < 27; i++) {
                int e = tid + i * 256;
                int c = e / NN, w = e - c * NN;
                Z[c * NPAD + w] = tmp[i];
            }
        }
    }

    // gates: r = sigmoid(accf + b_f), u = sigmoid(accu + b_u)
    const float bfv = b_f[o];
    const float buv = b_u[o];
    float ureg[18], rh[18];
#pragma unroll
    for (int j = 0; j < 18; j++) {
        float r = 1.f / (1.f + expf(-(accf[j] + bfv)));
        ureg[j] = 1.f / (1.f + expf(-(accu[j] + buv)));
        rh[j]   = r * hreg[j];
    }

    // ================= rebuild Z = [x ; r*h] =================
    __syncthreads();   // all phase-1 reads of Z done
    for (int i = tid; i < CX * NN; i += 256) {
        int c = i / NN, n = i - c * NN;
        Z[c * NPAD + n] = Xs[c * XSP + n];
    }
    {
        float* zp = Z + (CX + o) * NPAD + nb;
#pragma unroll
        for (int j = 0; j < 18; j++) zp[j] = rh[j];
    }

    // ================= phase 2: candidate =================
    float accc[18];
#pragma unroll
    for (int j = 0; j < 18; j++) accc[j] = 0.f;

    for (int k = 0; k < ORD; k++) {
        __syncthreads();

        const float* wc = g_Wt_c + k * CC * UU + o;
#pragma unroll 4
        for (int c = 0; c < CC; c++) {
            float wcv = wc[c * UU];
            const float2* zr = (const float2*)(Z + c * NPAD + nb);
#pragma unroll
            for (int j2 = 0; j2 < 9; j2++) {
                float2 z = zr[j2];
                accc[2 * j2]     += wcv * z.x;
                accc[2 * j2 + 1] += wcv * z.y;
            }
        }

        if (k < ORD - 1) {
            float tmp[27];
#pragma unroll
            for (int i = 0; i < 27; i++) {
                int e = tid + i * 256;
                int c = e / NN, w = e - c * NN;
                const float* zr = Z + c * NPAD;
                const float* ar = As + w * ASP;
                float s = 0.f;
#pragma unroll
                for (int n = 0; n < NN; n++) s += zr[n] * ar[n];
                tmp[i] = s;
            }
            __syncthreads();
#pragma unroll
            for (int i = 0; i < 27; i++) {
                int e = tid + i * 256;
                int c = e / NN, w = e - c * NN;
                Z[c * NPAD + w] = tmp[i];
            }
        }
    }

    // ================= output =================
    const float bcv = b_c[o];
    float* op = out + ((size_t)b * UU + o) * NN + nb;
#pragma unroll
    for (int j = 0; j < 18; j++) {
        float c = tanhf(accc[j] + bcv);
        float u = ureg[j];
        op[j] = u * hreg[j] + (1.f - u) * c;
    }
}

// ---------------------------------------------------------------------------
// Launch (graph-capturable: kernel launches only)
// ---------------------------------------------------------------------------
extern "C" void kernel_launch(void* const* d_in, const int* in_sizes, int n_in,
                              void* d_out, int out_size) {
    const float* x   = (const float*)d_in[0];   // [4096, 64, 36]
    const float* h   = (const float*)d_in[1];   // [4096, 128, 36]
    const float* adj = (const float*)d_in[2];   // [36, 36]
    const float* W_f = (const float*)d_in[3];   // [128, 768]
    const float* b_f = (const float*)d_in[4];   // [128]
    const float* W_u = (const float*)d_in[5];
    const float* b_u = (const float*)d_in[6];
    const float* W_c = (const float*)d_in[7];
    const float* b_c = (const float*)d_in[8];
    float* out = (float*)d_out;                 // [4096, 128, 36]

    transpose_w_kernel<<<(CCAT * UU + 255) / 256, 256>>>(W_f, W_u, W_c);
    gcgru_fused_kernel<<<BB, 256>>>(x, h, adj, b_f, b_u, b_c, out);
}

// round 6
// speedup vs baseline: 1.1879x; 1.1877x over previous
#include <cuda_runtime.h>
#include <math.h>

// Problem constants (fixed by setup_inputs)
#define BB   4096
#define CX   64
#define UU   128
#define NN   36
#define CC   192          // CX + UU
#define ORD  4            // order+1 diffusion levels (incl. self)
#define CCAT 768          // ORD * CC
#define NPAD 40           // padded Z row length (even -> pair-aligned)
#define ASP  38           // padded adj row length (even -> pair-aligned)

typedef unsigned long long ull;

// Transposed weights [cc][o] (device globals: allocation-free)
__device__ float g_Wt_f[CCAT * UU];
__device__ float g_Wt_u[CCAT * UU];
__device__ float g_Wt_c[CCAT * UU];

// ---- packed fp32x2 helpers (Blackwell sm_100+; exact IEEE fp32 numerics) ----
#define FMA2(d, a, b, c) \
    asm("fma.rn.f32x2 %0, %1, %2, %3;" : "=l"(d) : "l"(a), "l"(b), "l"(c))
#define PKDUP(v, f) \
    asm("mov.b64 %0, {%1, %1};" : "=l"(v) : "f"(f))
#define UNPK(lo, hi, v) \
    asm("mov.b64 {%0, %1}, %2;" : "=f"(lo), "=f"(hi) : "l"(v))

__device__ __forceinline__ float fsigmoid(float t) {
    return 1.0f / (1.0f + __expf(-t));
}
__device__ __forceinline__ float ftanh(float t) {
    return 2.0f / (1.0f + __expf(-2.0f * t)) - 1.0f;
}

// ---------------------------------------------------------------------------
// Transpose the three weight matrices [128, 768] -> [768, 128]
// ---------------------------------------------------------------------------
__global__ void transpose_w_kernel(const float* __restrict__ Wf,
                                   const float* __restrict__ Wu,
                                   const float* __restrict__ Wc) {
    int i = blockIdx.x * blockDim.x + threadIdx.x;   // over CCAT*UU
    if (i >= CCAT * UU) return;
    int cc = i / UU;
    int o  = i - cc * UU;
    int src = o * CCAT + cc;                          // W is [o][cc]
    g_Wt_f[i] = Wf[src];
    g_Wt_u[i] = Wu[src];
    g_Wt_c[i] = Wc[src];
}

// ---------------------------------------------------------------------------
// Fused GCGRU cell. One CTA per batch element, 256 threads, 2 CTAs/SM.
//   Phase 1: Z=[x;h], 4 diffusion levels (in-place hops), accumulate the
//            f and u gate GEMVs level-by-level -> r,u  (packed f32x2).
//   Phase 2: Z=[x;r*h], same diffusion, W_c GEMV -> candidate c.
//   Output:  u*h + (1-u)*tanh(c).
// Thread map: o = tid & 127 (output channel), n-half = (tid>>7)*18.
// ---------------------------------------------------------------------------
__global__ void __launch_bounds__(256, 2) gcgru_fused_kernel(
        const float* __restrict__ x, const float* __restrict__ h,
        const float* __restrict__ adj,
        const float* __restrict__ b_f, const float* __restrict__ b_u,
        const float* __restrict__ b_c, float* __restrict__ out) {
    __shared__ __align__(16) float Z [CC * NPAD];   // [192][40]  30.7 KB
    __shared__ __align__(16) float As[NN * ASP];    // [36][38]    5.5 KB

    const int b   = blockIdx.x;
    const int tid = threadIdx.x;
    const int o   = tid & 127;
    const int nb  = (tid >> 7) * 18;   // 0 or 18 (even -> 8B aligned)

    const float* xb = x + (size_t)b * CX * NN;
    const float* hb = h + (size_t)b * UU * NN;

    // ---------------- load inputs ----------------
    for (int i = tid; i < CX * NN; i += 256) {
        int c = i / NN, n = i - c * NN;
        Z[c * NPAD + n] = xb[i];
    }
    for (int i = tid; i < UU * NN; i += 256) {
        int c = i / NN, n = i - c * NN;
        Z[(CX + c) * NPAD + n] = hb[i];
    }
    for (int i = tid; i < NN * NN; i += 256) {
        int w = i / NN, n = i - w * NN;
        As[w * ASP + n] = adj[i];
    }

    // ================= phase 1: gates =================
    ull accf2[9], accu2[9];
#pragma unroll
    for (int j = 0; j < 9; j++) { accf2[j] = 0ULL; accu2[j] = 0ULL; }

    for (int k = 0; k < ORD; k++) {
        __syncthreads();   // Z level-k ready

        const float* wf = g_Wt_f + k * CC * UU + o;
        const float* wu = g_Wt_u + k * CC * UU + o;
#pragma unroll 4
        for (int c = 0; c < CC; c++) {
            ull wf2, wu2;
            PKDUP(wf2, wf[c * UU]);
            PKDUP(wu2, wu[c * UU]);
            const ull* zr = (const ull*)(Z + c * NPAD + nb);
#pragma unroll
            for (int j = 0; j < 9; j++) {
                ull zv = zr[j];               // broadcast LDS.64
                FMA2(accf2[j], wf2, zv, accf2[j]);
                FMA2(accu2[j], wu2, zv, accu2[j]);
            }
        }

        if (k < ORD - 1) {
            // in-place hop: Z[c][w] <- sum_n Z[c][n] * adj[w][n]
            float tmp[27];                     // 192*36/256 = 27
#pragma unroll
            for (int i = 0; i < 27; i++) {
                int e = tid + i * 256;
                int c = e / NN, w = e - c * NN;
                const ull* zr = (const ull*)(Z + c * NPAD);
                const ull* ar = (const ull*)(As + w * ASP);
                ull s2 = 0ULL;
#pragma unroll
                for (int n2 = 0; n2 < 18; n2++) FMA2(s2, zr[n2], ar[n2], s2);
                float lo, hi; UNPK(lo, hi, s2);
                tmp[i] = lo + hi;
            }
            __syncthreads();                   // all reads of Z done
#pragma unroll
            for (int i = 0; i < 27; i++) {
                int e = tid + i * 256;
                int c = e / NN, w = e - c * NN;
                Z[c * NPAD + w] = tmp[i];
            }
        }
    }

    // gates: r = sigmoid(accf + b_f), u = sigmoid(accu + b_u)
    const float bfv = b_f[o];
    const float buv = b_u[o];
    float ureg[18], rh[18];
    {
        const float* hp = hb + o * NN + nb;
#pragma unroll
        for (int j = 0; j < 9; j++) {
            float f0, f1, u0, u1;
            UNPK(f0, f1, accf2[j]);
            UNPK(u0, u1, accu2[j]);
            float r0 = fsigmoid(f0 + bfv);
            float r1 = fsigmoid(f1 + bfv);
            ureg[2 * j]     = fsigmoid(u0 + buv);
            ureg[2 * j + 1] = fsigmoid(u1 + buv);
            rh[2 * j]       = r0 * hp[2 * j];
            rh[2 * j + 1]   = r1 * hp[2 * j + 1];
        }
    }

    // ================= rebuild Z = [x ; r*h] =================
    __syncthreads();   // all phase-1 reads of Z done
    for (int i = tid; i < CX * NN; i += 256) {
        int c = i / NN, n = i - c * NN;
        Z[c * NPAD + n] = xb[i];
    }
    {
        float* zp = Z + (CX + o) * NPAD + nb;
#pragma unroll
        for (int j = 0; j < 18; j++) zp[j] = rh[j];
    }

    // ================= phase 2: candidate =================
    ull accc2[9];
#pragma unroll
    for (int j = 0; j < 9; j++) accc2[j] = 0ULL;

    for (int k = 0; k < ORD; k++) {
        __syncthreads();

        const float* wc = g_Wt_c + k * CC * UU + o;
#pragma unroll 4
        for (int c = 0; c < CC; c++) {
            ull wc2;
            PKDUP(wc2, wc[c * UU]);
            const ull* zr = (const ull*)(Z + c * NPAD + nb);
#pragma unroll
            for (int j = 0; j < 9; j++) {
                FMA2(accc2[j], wc2, zr[j], accc2[j]);
            }
        }

        if (k < ORD - 1) {
            float tmp[27];
#pragma unroll
            for (int i = 0; i < 27; i++) {
                int e = tid + i * 256;
                int c = e / NN, w = e - c * NN;
                const ull* zr = (const ull*)(Z + c * NPAD);
                const ull* ar = (const ull*)(As + w * ASP);
                ull s2 = 0ULL;
#pragma unroll
                for (int n2 = 0; n2 < 18; n2++) FMA2(s2, zr[n2], ar[n2], s2);
                float lo, hi; UNPK(lo, hi, s2);
                tmp[i] = lo + hi;
            }
            __syncthreads();
#pragma unroll
            for (int i = 0; i < 27; i++) {
                int e = tid + i * 256;
                int c = e / NN, w = e - c * NN;
                Z[c * NPAD + w] = tmp[i];
            }
        }
    }

    // ================= output =================
    const float bcv = b_c[o];
    const float* hp = hb + o * NN + nb;
    float* op = out + ((size_t)b * UU + o) * NN + nb;
#pragma unroll
    for (int j = 0; j < 9; j++) {
        float c0, c1;
        UNPK(c0, c1, accc2[j]);
        c0 = ftanh(c0 + bcv);
        c1 = ftanh(c1 + bcv);
        float u0 = ureg[2 * j], u1 = ureg[2 * j + 1];
        op[2 * j]     = u0 * hp[2 * j]     + (1.f - u0) * c0;
        op[2 * j + 1] = u1 * hp[2 * j + 1] + (1.f - u1) * c1;
    }
}

// ---------------------------------------------------------------------------
// Launch (graph-capturable: kernel launches only)
// ---------------------------------------------------------------------------
extern "C" void kernel_launch(void* const* d_in, const int* in_sizes, int n_in,
                              void* d_out, int out_size) {
    const float* x   = (const float*)d_in[0];   // [4096, 64, 36]
    const float* h   = (const float*)d_in[1];   // [4096, 128, 36]
    const float* adj = (const float*)d_in[2];   // [36, 36]
    const float* W_f = (const float*)d_in[3];   // [128, 768]
    const float* b_f = (const float*)d_in[4];   // [128]
    const float* W_u = (const float*)d_in[5];
    const float* b_u = (const float*)d_in[6];
    const float* W_c = (const float*)d_in[7];
    const float* b_c = (const float*)d_in[8];
    float* out = (float*)d_out;                 // [4096, 128, 36]

    transpose_w_kernel<<<(CCAT * UU + 255) / 256, 256>>>(W_f, W_u, W_c);
    gcgru_fused_kernel<<<BB, 256>>>(x, h, adj, b_f, b_u, b_c, out);
}